// round 7
// baseline (speedup 1.0000x reference)
#include <cuda_runtime.h>
#include <cuda_bf16.h>
#include <cstdint>

// ---------------------------------------------------------------------------
// NeuralODE persistent kernel, round 7:
//  Two software-staggered step-chains (A = rows 0-15, B = rows 16-31, B half a
//  step behind). Each round = 3 segments, each pairing two INDEPENDENT
//  GEMM+epilogue blocks from different chains/stages:
//    seg1: G2_A + G1_B | seg2: G3_A + G2_B | seg3: G1_A(next) + G3_B
//  so one chain's epilogue/drain bubbles are filled by the other chain's MMAs.
//  3 plain __syncthreads per round (no branchy mbarrier waits).
//  W2/W3 B-fragments + biases register-resident, shared by both chains.
//  Chain activation buffers overlay the dead W2/W3 smem planes.
// ---------------------------------------------------------------------------

namespace {

constexpr int B_    = 4096;
constexpr int S_    = 64;
constexpr int H_    = 256;
constexpr int MROWS = 32;              // rows per CTA (2 chains x 16)
constexpr int CTAS  = B_ / MROWS;      // 128
constexpr int NTH   = 256;             // 8 warps

// u32 strides (stride % 8 == 4 -> conflict-free ldmatrix phases)
constexpr int HSTR = 132;
constexpr int XSTR = 36;

// smem layout (bytes)
constexpr int SM_W1P0 = 0;                 // 16384 (live)
constexpr int SM_W1P1 = 16384;             // 16384 (live)
constexpr int SM_W2P0 = 32768;             // 65536 (dead after reg load)
constexpr int SM_W2P1 = 98304;             // 65536 (dead)
constexpr int SM_W3P0 = 163840;            // 16384 (dead)
constexpr int SM_W3P1 = 180224;            // 16384 (dead)
constexpr int SM_ENDW = 196608;

// chain buffers overlay the dead region starting at SM_W2P0
constexpr int HB = 16 * HSTR * 4;          // 8448 bytes (16-row h buffer)
constexpr int XBB = 16 * XSTR * 4;         // 2304 bytes (16-row x buffer)
constexpr int SM_H1A = SM_W2P0;            // all offsets are 128B-multiples ->
constexpr int SM_H1B = SM_H1A + HB;        // identical bank patterns
constexpr int SM_H2A = SM_H1B + HB;
constexpr int SM_H2B = SM_H2A + HB;
constexpr int SM_XA  = SM_H2B + HB;
constexpr int SM_XB2 = SM_XA + XBB;
constexpr int SMEM_BYTES = SM_ENDW + 256;

__device__ __forceinline__ uint32_t pack_bf16(float lo, float hi) {
    __nv_bfloat162 v = __floats2bfloat162_rn(lo, hi);
    return *reinterpret_cast<uint32_t*>(&v);
}

__device__ __forceinline__ uint32_t tanh_bf16x2(uint32_t v) {
    uint32_t r;
    asm("tanh.approx.bf16x2 %0, %1;" : "=r"(r) : "r"(v));
    return r;
}

__device__ __forceinline__ void ldsm_x4(uint32_t& r0, uint32_t& r1,
                                        uint32_t& r2, uint32_t& r3,
                                        uint32_t addr) {
    asm volatile("ldmatrix.sync.aligned.m8n8.x4.shared.b16 {%0,%1,%2,%3}, [%4];"
                 : "=r"(r0), "=r"(r1), "=r"(r2), "=r"(r3) : "r"(addr));
}

__device__ __forceinline__ void mma16816(float* d,
                                         uint32_t a0, uint32_t a1, uint32_t a2, uint32_t a3,
                                         uint32_t b0, uint32_t b1) {
    asm volatile(
        "mma.sync.aligned.m16n8k16.row.col.f32.bf16.bf16.f32 "
        "{%0,%1,%2,%3},{%4,%5,%6,%7},{%8,%9},{%0,%1,%2,%3};\n"
        : "+f"(d[0]), "+f"(d[1]), "+f"(d[2]), "+f"(d[3])
        : "r"(a0), "r"(a1), "r"(a2), "r"(a3), "r"(b0), "r"(b1));
}

// Shuffle fp32 W[K][N] (row-major) into one bf16x2 B-fragment plane.
template <int NKB, int LOG2NKB>
__device__ void fill_plane(uint32_t* plane, const float* __restrict__ W,
                           int N, int koff, int tid) {
    const int total = N * NKB * 4;
    for (int e = tid; e < total; e += NTH) {
        int gg   = e & 7;
        int tt   = (e >> 3) & 3;
        int kbnt = e >> 5;
        int kb   = kbnt & (NKB - 1);
        int nt   = kbnt >> LOG2NKB;
        int n    = nt * 8 + gg;
        int k0   = kb * 16 + tt * 2 + koff;
        plane[e] = pack_bf16(W[k0 * N + n], W[(k0 + 1) * N + n]);
    }
}

} // namespace

extern "C" __global__ void __launch_bounds__(NTH, 1)
neuralode_persistent_kernel(const float* __restrict__ x0,
                            const float* __restrict__ W1, const float* __restrict__ b1,
                            const float* __restrict__ W2, const float* __restrict__ b2,
                            const float* __restrict__ W3, const float* __restrict__ b3,
                            const float* __restrict__ dt_scale,
                            const int*   __restrict__ num_steps,
                            float* __restrict__ out)
{
    extern __shared__ unsigned char smem_raw[];
    uint32_t* w1p0 = reinterpret_cast<uint32_t*>(smem_raw + SM_W1P0);
    uint32_t* w1p1 = reinterpret_cast<uint32_t*>(smem_raw + SM_W1P1);
    uint32_t* w2p0 = reinterpret_cast<uint32_t*>(smem_raw + SM_W2P0);
    uint32_t* w2p1 = reinterpret_cast<uint32_t*>(smem_raw + SM_W2P1);
    uint32_t* w3p0 = reinterpret_cast<uint32_t*>(smem_raw + SM_W3P0);
    uint32_t* w3p1 = reinterpret_cast<uint32_t*>(smem_raw + SM_W3P1);
    // chain buffers (generic pointers for STS)
    uint32_t* h1p[2] = { reinterpret_cast<uint32_t*>(smem_raw + SM_H1A),
                         reinterpret_cast<uint32_t*>(smem_raw + SM_H1B) };
    uint32_t* h2p[2] = { reinterpret_cast<uint32_t*>(smem_raw + SM_H2A),
                         reinterpret_cast<uint32_t*>(smem_raw + SM_H2B) };
    uint32_t* xbp[2] = { reinterpret_cast<uint32_t*>(smem_raw + SM_XA),
                         reinterpret_cast<uint32_t*>(smem_raw + SM_XB2) };

    const int tid = threadIdx.x;

    // ---- one-time weight shuffle into fragment-ordered smem planes ----
    fill_plane<4, 2>(w1p0, W1, H_, 0, tid);
    fill_plane<4, 2>(w1p1, W1, H_, 8, tid);
    fill_plane<16, 4>(w2p0, W2, H_, 0, tid);
    fill_plane<16, 4>(w2p1, W2, H_, 8, tid);
    fill_plane<16, 4>(w3p0, W3, S_, 0, tid);
    fill_plane<16, 4>(w3p1, W3, S_, 8, tid);

    const int   nsteps  = num_steps[0];
    const float dts     = dt_scale[0] * 0.01f;
    const int   row0    = blockIdx.x * MROWS;
    const long  ostride = (long)(nsteps + 1) * S_;

    // ---- t=0: trajectory[., 0, .] = x0 ----
    for (int i = tid; i < MROWS * S_; i += NTH) {
        int r = i >> 6, c = i & 63;
        out[(long)(row0 + r) * ostride + c] = x0[(row0 + r) * S_ + c];
    }

    // ---- warp/lane decomposition ----
    const int lane = tid & 31;
    const int g = lane >> 2, t = lane & 3;
    const int ng  = tid >> 5;          // 0..7 column group
    const int tg  = t * 8 + g;

    // ldmatrix lane-address mapping: quad q -> (row-half, k-half)
    const int q     = lane >> 3;
    const int rrow  = (lane & 7) | ((q & 1) << 3);   // 0..15
    const int koffu = (q >> 1) << 2;                 // 0 or 4 u32

    const uint32_t sbase = (uint32_t)__cvta_generic_to_shared(smem_raw);
    const uint32_t h1a[2] = { sbase + SM_H1A + (rrow * HSTR + koffu) * 4,
                              sbase + SM_H1B + (rrow * HSTR + koffu) * 4 };
    const uint32_t h2a[2] = { sbase + SM_H2A + (rrow * HSTR + koffu) * 4,
                              sbase + SM_H2B + (rrow * HSTR + koffu) * 4 };
    const uint32_t xba[2] = { sbase + SM_XA  + (rrow * XSTR + koffu) * 4,
                              sbase + SM_XB2 + (rrow * XSTR + koffu) * 4 };

    __syncthreads();   // weight planes ready

    // ---- register-resident weight fragments (shared by both chains) ----
    uint32_t wb2a[4][16], wb2b[4][16];
#pragma unroll
    for (int j = 0; j < 4; ++j)
#pragma unroll
        for (int kb = 0; kb < 16; ++kb) {
            int idx = ((ng * 4 + j) * 16 + kb) * 32 + tg;
            wb2a[j][kb] = w2p0[idx];
            wb2b[j][kb] = w2p1[idx];
        }
    uint32_t wb3a[16], wb3b[16];
#pragma unroll
    for (int kb = 0; kb < 16; ++kb) {
        int idx = (ng * 16 + kb) * 32 + tg;
        wb3a[kb] = w3p0[idx];
        wb3b[kb] = w3p1[idx];
    }

    // ---- register-resident biases ----
    float pb1[4][2], pb2[4][2], pb3[2];
#pragma unroll
    for (int j = 0; j < 4; ++j) {
        int c = (ng * 4 + j) * 8 + t * 2;
        pb1[j][0] = b1[c];     pb1[j][1] = b1[c + 1];
        pb2[j][0] = b2[c];     pb2[j][1] = b2[c + 1];
    }
    {
        int c = ng * 8 + t * 2;
        pb3[0] = b3[c]; pb3[1] = b3[c + 1];
    }

    __syncthreads();   // all W2/W3 plane reads done before buffers overwrite

    // ---- x state in registers, one 16-row chain per c ----
    float xr[2][4];
#pragma unroll
    for (int c = 0; c < 2; ++c) {
        int r = c * 16 + g;
        int colb = ng * 8 + t * 2;
        const float* p = x0 + (long)(row0 + r) * S_ + colb;
        xr[c][0] = p[0];
        xr[c][1] = p[1];
        xr[c][2] = p[8 * S_];
        xr[c][3] = p[8 * S_ + 1];
        int pidx = ng * 4 + t;
        xbp[c][g * XSTR + pidx]       = pack_bf16(xr[c][0], xr[c][1]);
        xbp[c][(g + 8) * XSTR + pidx] = pack_bf16(xr[c][2], xr[c][3]);
    }
    __syncthreads();   // xb ready

    // ---- GEMM/epilogue building blocks (all fully unrolled) ----
    auto do_g1 = [&](uint32_t xaddr, float (&acc)[4][4]) {
#pragma unroll
        for (int j = 0; j < 4; ++j)
#pragma unroll
            for (int q2 = 0; q2 < 4; ++q2) acc[j][q2] = 0.f;
#pragma unroll
        for (int kb = 0; kb < 4; ++kb) {
            uint32_t a0, a1v, a2, a3;
            ldsm_x4(a0, a1v, a2, a3, xaddr + kb * 32);
#pragma unroll
            for (int j = 0; j < 4; ++j) {
                int idx = ((ng * 4 + j) * 4 + kb) * 32 + tg;
                mma16816(acc[j], a0, a1v, a2, a3, w1p0[idx], w1p1[idx]);
            }
        }
    };
    auto do_g2 = [&](uint32_t haddr, float (&acc)[4][4]) {
#pragma unroll
        for (int j = 0; j < 4; ++j)
#pragma unroll
            for (int q2 = 0; q2 < 4; ++q2) acc[j][q2] = 0.f;
#pragma unroll
        for (int kb = 0; kb < 16; ++kb) {
            uint32_t a0, a1v, a2, a3;
            ldsm_x4(a0, a1v, a2, a3, haddr + kb * 32);
#pragma unroll
            for (int j = 0; j < 4; ++j)
                mma16816(acc[j], a0, a1v, a2, a3, wb2a[j][kb], wb2b[j][kb]);
        }
    };
    auto do_g3 = [&](uint32_t haddr, float (&acc3)[4]) {
#pragma unroll
        for (int q2 = 0; q2 < 4; ++q2) acc3[q2] = 0.f;
#pragma unroll
        for (int kb = 0; kb < 16; ++kb) {
            uint32_t a0, a1v, a2, a3;
            ldsm_x4(a0, a1v, a2, a3, haddr + kb * 32);
            mma16816(acc3, a0, a1v, a2, a3, wb3a[kb], wb3b[kb]);
        }
    };
    auto epi_h = [&](uint32_t* dst, float (&acc)[4][4], float (&pb)[4][2]) {
#pragma unroll
        for (int j = 0; j < 4; ++j) {
            int pidx = (ng * 4 + j) * 4 + t;
            dst[g * HSTR + pidx] =
                tanh_bf16x2(pack_bf16(acc[j][0] + pb[j][0],
                                      acc[j][1] + pb[j][1]));
            dst[(g + 8) * HSTR + pidx] =
                tanh_bf16x2(pack_bf16(acc[j][2] + pb[j][0],
                                      acc[j][3] + pb[j][1]));
        }
    };
    auto epi_x = [&](int c, int step, float (&acc3)[4]) {
        int r = c * 16 + g;
        int colb = ng * 8 + t * 2;
        xr[c][0] += (acc3[0] + pb3[0]) * dts;
        xr[c][1] += (acc3[1] + pb3[1]) * dts;
        xr[c][2] += (acc3[2] + pb3[0]) * dts;
        xr[c][3] += (acc3[3] + pb3[1]) * dts;
        float* orow = out + (long)(row0 + r) * ostride
                    + (long)(step + 1) * S_ + colb;
        __stcs(reinterpret_cast<float2*>(orow),
               make_float2(xr[c][0], xr[c][1]));
        __stcs(reinterpret_cast<float2*>(orow + 8 * ostride),
               make_float2(xr[c][2], xr[c][3]));
        int pidx = ng * 4 + t;
        xbp[c][g * XSTR + pidx]       = pack_bf16(xr[c][0], xr[c][1]);
        xbp[c][(g + 8) * XSTR + pidx] = pack_bf16(xr[c][2], xr[c][3]);
    };

    // ---- prologue: chain A runs G1(0)+E1(0) so it leads by one stage ----
    {
        float acc[4][4];
        do_g1(xba[0], acc);
        epi_h(h1p[0], acc, pb1);
    }
    __syncthreads();

    // ======================= main round loop ==========================
    // Round r:  seg1: G2_A(r)   + G1_B(r)
    //           seg2: G3_A(r)   + G2_B(r)   (E3_A stores step r+1 for A)
    //           seg3: G1_A(r+1) + G3_B(r)   (E3_B stores step r+1 for B)
    // WAR hazards: every buffer's write/read pairs are separated by a bar
    // (h1_A: W seg3 / R seg1; h2_A: W seg1 / R seg2; xb_A: W seg2 / R seg3;
    //  h1_B: W seg1 / R seg2; h2_B: W seg2 / R seg3; xb_B: W seg3 / R seg1).
    for (int r = 0; r < nsteps; ++r) {
        // ---- seg1 ----
        {
            float accA[4][4], accB[4][4];
            do_g2(h1a[0], accA);       // chain A GEMM2
            do_g1(xba[1], accB);       // chain B GEMM1 (independent)
            epi_h(h2p[0], accA, pb2);
            epi_h(h1p[1], accB, pb1);
        }
        __syncthreads();

        // ---- seg2 ----
        {
            float acc3A[4], accB[4][4];
            do_g3(h2a[0], acc3A);      // chain A GEMM3
            do_g2(h1a[1], accB);       // chain B GEMM2 (independent)
            epi_x(0, r, acc3A);        // A: x update + store step r+1
            epi_h(h2p[1], accB, pb2);
        }
        __syncthreads();

        // ---- seg3 ----
        {
            float accA[4][4], acc3B[4];
            do_g1(xba[0], accA);       // chain A GEMM1 of step r+1
            do_g3(h2a[1], acc3B);      // chain B GEMM3 (independent)
            epi_h(h1p[0], accA, pb1);  // (last round: h1_A unused, harmless)
            epi_x(1, r, acc3B);        // B: x update + store step r+1
        }
        __syncthreads();
    }
}

extern "C" void kernel_launch(void* const* d_in, const int* in_sizes, int n_in,
                              void* d_out, int out_size)
{
    (void)in_sizes; (void)n_in; (void)out_size;
    const float* x0       = (const float*)d_in[0];
    const float* W1       = (const float*)d_in[1];
    const float* b1       = (const float*)d_in[2];
    const float* W2       = (const float*)d_in[3];
    const float* b2       = (const float*)d_in[4];
    const float* W3       = (const float*)d_in[5];
    const float* b3       = (const float*)d_in[6];
    const float* dt_scale = (const float*)d_in[7];
    const int*   nsteps   = (const int*)d_in[8];
    float*       out      = (float*)d_out;

    cudaFuncSetAttribute(neuralode_persistent_kernel,
                         cudaFuncAttributeMaxDynamicSharedMemorySize, SMEM_BYTES);
    neuralode_persistent_kernel<<<CTAS, NTH, SMEM_BYTES>>>(
        x0, W1, b1, W2, b2, W3, b3, dt_scale, nsteps, out);
}

// round 14
// speedup vs baseline: 1.3127x; 1.3127x over previous
#include <cuda_runtime.h>
#include <cuda_bf16.h>
#include <cstdint>

// ---------------------------------------------------------------------------
// NeuralODE persistent kernel, round 12:
//  R11 (fp8 e4m3 QMMA for the two H-sized GEMMs) with the cvt syntax fixed:
//  e4m3x2 conversion destinations are 16-bit -> "=h" operands.
//  - G1 (x@W1) stays bf16 HMMA; G2 (h1@W2), G3 (h2@W3) run e4m3 m16n8k32.
//  - h tiles + W2/W3 frags scaled x16; epilogues fold 1/256.
//  - W1/W2/W3 fragments + biases all register-resident.
// ---------------------------------------------------------------------------

namespace {

constexpr int B_    = 4096;
constexpr int S_    = 64;
constexpr int H_    = 256;
constexpr int MROWS = 32;              // rows per CTA
constexpr int CTAS  = B_ / MROWS;      // 128
constexpr int NTH   = 256;             // 8 warps

constexpr int XSTR  = 36;              // x tile u32 stride (stride%8==4)
constexpr int HS    = 272;             // h tile BYTE stride (272%128==16)

// smem layout (bytes, 128-aligned tiles)
constexpr int SM_X  = 0;                       // 32*36*4 = 4608
constexpr int SM_H1 = 4608;                    // 32*272  = 8704
constexpr int SM_H2 = 13312;                   // 8704
constexpr int SMEM_BYTES = 22016 + 256;

__device__ __forceinline__ uint32_t pack_bf16(float lo, float hi) {
    __nv_bfloat162 v = __floats2bfloat162_rn(lo, hi);
    return *reinterpret_cast<uint32_t*>(&v);
}

// f32 pair -> f16x2 -> tanh -> *16 -> e4m3x2 (u16: low byte = lo, high = hi)
__device__ __forceinline__ uint16_t tanh16_e4m3(float hi, float lo) {
    uint32_t ph, th, ts;
    uint16_t e;
    asm("cvt.rn.f16x2.f32 %0, %1, %2;" : "=r"(ph) : "f"(hi), "f"(lo));
    asm("tanh.approx.f16x2 %0, %1;" : "=r"(th) : "r"(ph));
    asm("mul.rn.f16x2 %0, %1, %2;" : "=r"(ts) : "r"(th), "r"(0x4C004C00u)); // *16
    asm("cvt.rn.satfinite.e4m3x2.f16x2 %0, %1;" : "=h"(e) : "r"(ts));
    return e;
}

// pack 4 f32 (already scaled) into 4 e4m3 bytes, k-ascending byte order
__device__ __forceinline__ uint32_t pk_e4m3x4(float f0, float f1, float f2, float f3) {
    uint16_t lo, hi;
    uint32_t d;
    asm("cvt.rn.satfinite.e4m3x2.f32 %0, %1, %2;" : "=h"(lo) : "f"(f1), "f"(f0));
    asm("cvt.rn.satfinite.e4m3x2.f32 %0, %1, %2;" : "=h"(hi) : "f"(f3), "f"(f2));
    asm("mov.b32 %0, {%1, %2};" : "=r"(d) : "h"(lo), "h"(hi));
    return d;
}

__device__ __forceinline__ void ldsm_x4(uint32_t& r0, uint32_t& r1,
                                        uint32_t& r2, uint32_t& r3,
                                        uint32_t addr) {
    asm volatile("ldmatrix.sync.aligned.m8n8.x4.shared.b16 {%0,%1,%2,%3}, [%4];"
                 : "=r"(r0), "=r"(r1), "=r"(r2), "=r"(r3) : "r"(addr));
}

__device__ __forceinline__ void mma16816(float* d,
                                         uint32_t a0, uint32_t a1, uint32_t a2, uint32_t a3,
                                         uint32_t b0, uint32_t b1) {
    asm volatile(
        "mma.sync.aligned.m16n8k16.row.col.f32.bf16.bf16.f32 "
        "{%0,%1,%2,%3},{%4,%5,%6,%7},{%8,%9},{%0,%1,%2,%3};\n"
        : "+f"(d[0]), "+f"(d[1]), "+f"(d[2]), "+f"(d[3])
        : "r"(a0), "r"(a1), "r"(a2), "r"(a3), "r"(b0), "r"(b1));
}

__device__ __forceinline__ void qmma(float* d,
                                     uint32_t a0, uint32_t a1, uint32_t a2, uint32_t a3,
                                     uint32_t b0, uint32_t b1) {
    asm volatile(
        "mma.sync.aligned.m16n8k32.row.col.f32.e4m3.e4m3.f32 "
        "{%0,%1,%2,%3},{%4,%5,%6,%7},{%8,%9},{%0,%1,%2,%3};\n"
        : "+f"(d[0]), "+f"(d[1]), "+f"(d[2]), "+f"(d[3])
        : "r"(a0), "r"(a1), "r"(a2), "r"(a3), "r"(b0), "r"(b1));
}

} // namespace

extern "C" __global__ void __launch_bounds__(NTH, 1)
neuralode_persistent_kernel(const float* __restrict__ x0,
                            const float* __restrict__ W1, const float* __restrict__ b1,
                            const float* __restrict__ W2, const float* __restrict__ b2,
                            const float* __restrict__ W3, const float* __restrict__ b3,
                            const float* __restrict__ dt_scale,
                            const int*   __restrict__ num_steps,
                            float* __restrict__ out)
{
    extern __shared__ unsigned char smem_raw[];
    uint32_t* xb = reinterpret_cast<uint32_t*>(smem_raw + SM_X);

    const int tid  = threadIdx.x;
    const int lane = tid & 31;
    const int g = lane >> 2, t = lane & 3;
    const int ng = tid >> 5;               // warp = n-column group 0..7

    const int   nsteps  = num_steps[0];
    const float dts     = dt_scale[0] * 0.01f;
    const float dts256  = dts * (1.0f / 256.0f);
    const float inv256  = 1.0f / 256.0f;
    const int   row0    = blockIdx.x * MROWS;
    const long  ostride = (long)(nsteps + 1) * S_;

    // ---- t=0: trajectory[., 0, .] = x0 ----
    for (int i = tid; i < MROWS * S_; i += NTH) {
        int r = i >> 6, c = i & 63;
        out[(long)(row0 + r) * ostride + c] = x0[(row0 + r) * S_ + c];
    }

    // ---- register-resident weight fragments ----
    // W1 (bf16 B-frags): k0 = kb*16 + 2t (+8 for p1), n = ng*32 + j*8 + g
    uint32_t wb1p0[4][4], wb1p1[4][4];
#pragma unroll
    for (int j = 0; j < 4; ++j) {
        int n = ng * 32 + j * 8 + g;
#pragma unroll
        for (int kb = 0; kb < 4; ++kb) {
            int k0 = kb * 16 + 2 * t;
            wb1p0[j][kb] = pack_bf16(W1[k0 * H_ + n],       W1[(k0 + 1) * H_ + n]);
            wb1p1[j][kb] = pack_bf16(W1[(k0 + 8) * H_ + n], W1[(k0 + 9) * H_ + n]);
        }
    }
    // W2 (e4m3, scaled x16): k0 = kb*32 + 4t (a) / +16 (b)
    uint32_t wb2a[4][8], wb2b[4][8];
#pragma unroll
    for (int j = 0; j < 4; ++j) {
        int n = ng * 32 + j * 8 + g;
#pragma unroll
        for (int kb = 0; kb < 8; ++kb) {
            int k0 = kb * 32 + 4 * t;
            wb2a[j][kb] = pk_e4m3x4(16.f * W2[k0 * H_ + n],      16.f * W2[(k0+1) * H_ + n],
                                    16.f * W2[(k0+2) * H_ + n],  16.f * W2[(k0+3) * H_ + n]);
            wb2b[j][kb] = pk_e4m3x4(16.f * W2[(k0+16) * H_ + n], 16.f * W2[(k0+17) * H_ + n],
                                    16.f * W2[(k0+18) * H_ + n], 16.f * W2[(k0+19) * H_ + n]);
        }
    }
    // W3 (e4m3, scaled x16): n = ng*8 + g (one n-tile per warp)
    uint32_t wb3a[8], wb3b[8];
    {
        int n = ng * 8 + g;
#pragma unroll
        for (int kb = 0; kb < 8; ++kb) {
            int k0 = kb * 32 + 4 * t;
            wb3a[kb] = pk_e4m3x4(16.f * W3[k0 * S_ + n],      16.f * W3[(k0+1) * S_ + n],
                                 16.f * W3[(k0+2) * S_ + n],  16.f * W3[(k0+3) * S_ + n]);
            wb3b[kb] = pk_e4m3x4(16.f * W3[(k0+16) * S_ + n], 16.f * W3[(k0+17) * S_ + n],
                                 16.f * W3[(k0+18) * S_ + n], 16.f * W3[(k0+19) * S_ + n]);
        }
    }

    // ---- biases (fragment layout) ----
    float pb1[4][2], pb2[4][2], pb3d[2];
#pragma unroll
    for (int j = 0; j < 4; ++j) {
        int c = (ng * 4 + j) * 8 + t * 2;
        pb1[j][0] = b1[c];  pb1[j][1] = b1[c + 1];
        pb2[j][0] = b2[c];  pb2[j][1] = b2[c + 1];
    }
    {
        int c = ng * 8 + t * 2;
        pb3d[0] = b3[c] * dts;  pb3d[1] = b3[c + 1] * dts;
    }

    // ---- ldmatrix addresses ----
    const int q     = lane >> 3;
    const int rrow  = (lane & 7) | ((q & 1) << 3);   // 0..15
    const uint32_t sbase = (uint32_t)__cvta_generic_to_shared(smem_raw);
    uint32_t xba[2], h1a[2], h2a[2];
#pragma unroll
    for (int mt = 0; mt < 2; ++mt) {
        xba[mt] = sbase + SM_X  + ((mt * 16 + rrow) * XSTR + ((q >> 1) << 2)) * 4;
        h1a[mt] = sbase + SM_H1 + (mt * 16 + rrow) * HS + (q >> 1) * 16;
        h2a[mt] = sbase + SM_H2 + (mt * 16 + rrow) * HS + (q >> 1) * 16;
    }

    // ---- x state registers + x tile (bf16) ----
    float xr[2][4];
#pragma unroll
    for (int mt = 0; mt < 2; ++mt) {
        int r = mt * 16 + g;
        int colb = ng * 8 + t * 2;
        const float* p = x0 + (long)(row0 + r) * S_ + colb;
        xr[mt][0] = p[0];
        xr[mt][1] = p[1];
        xr[mt][2] = p[8 * S_];
        xr[mt][3] = p[8 * S_ + 1];
        int pidx = ng * 4 + t;
        xb[r * XSTR + pidx]       = pack_bf16(xr[mt][0], xr[mt][1]);
        xb[(r + 8) * XSTR + pidx] = pack_bf16(xr[mt][2], xr[mt][3]);
    }
    __syncthreads();

    // ======================= main time-step loop ==========================
    for (int step = 0; step < nsteps; ++step) {
        float acc[2][4][4];

        // ---- GEMM1 (bf16): [32,64] @ W1[64,256] ----
#pragma unroll
        for (int mt = 0; mt < 2; ++mt)
#pragma unroll
            for (int j = 0; j < 4; ++j)
#pragma unroll
                for (int u = 0; u < 4; ++u) acc[mt][j][u] = 0.f;

#pragma unroll
        for (int kb = 0; kb < 4; ++kb) {
            uint32_t a[2][4];
#pragma unroll
            for (int mt = 0; mt < 2; ++mt)
                ldsm_x4(a[mt][0], a[mt][1], a[mt][2], a[mt][3], xba[mt] + kb * 32);
#pragma unroll
            for (int j = 0; j < 4; ++j)
#pragma unroll
                for (int mt = 0; mt < 2; ++mt)
                    mma16816(acc[mt][j], a[mt][0], a[mt][1], a[mt][2], a[mt][3],
                             wb1p0[j][kb], wb1p1[j][kb]);
        }
        // E1: h1 = e4m3(16 * tanh(acc + b1))
#pragma unroll
        for (int mt = 0; mt < 2; ++mt)
#pragma unroll
            for (int j = 0; j < 4; ++j) {
                float a0 = acc[mt][j][0] + pb1[j][0];
                float a1 = acc[mt][j][1] + pb1[j][1];
                float a2 = acc[mt][j][2] + pb1[j][0];
                float a3 = acc[mt][j][3] + pb1[j][1];
                int col = ng * 32 + j * 8 + 2 * t;
                int r = mt * 16 + g;
                *reinterpret_cast<uint16_t*>(smem_raw + SM_H1 + r * HS + col) =
                    tanh16_e4m3(a1, a0);
                *reinterpret_cast<uint16_t*>(smem_raw + SM_H1 + (r + 8) * HS + col) =
                    tanh16_e4m3(a3, a2);
            }
        __syncthreads();   // bar A: h1 ready

        // ---- GEMM2 (e4m3): [32,256] @ W2[256,256], acc = 256*true ----
#pragma unroll
        for (int mt = 0; mt < 2; ++mt)
#pragma unroll
            for (int j = 0; j < 4; ++j)
#pragma unroll
                for (int u = 0; u < 4; ++u) acc[mt][j][u] = 0.f;

#pragma unroll
        for (int kb = 0; kb < 8; ++kb) {
            uint32_t a[2][4];
#pragma unroll
            for (int mt = 0; mt < 2; ++mt)
                ldsm_x4(a[mt][0], a[mt][1], a[mt][2], a[mt][3], h1a[mt] + kb * 32);
#pragma unroll
            for (int j = 0; j < 4; ++j)
#pragma unroll
                for (int mt = 0; mt < 2; ++mt)
                    qmma(acc[mt][j], a[mt][0], a[mt][1], a[mt][2], a[mt][3],
                         wb2a[j][kb], wb2b[j][kb]);
        }

        // E2: h2 = e4m3(16 * tanh(acc/256 + b2))  (distinct buffer)
#pragma unroll
        for (int mt = 0; mt < 2; ++mt)
#pragma unroll
            for (int j = 0; j < 4; ++j) {
                float a0 = fmaf(acc[mt][j][0], inv256, pb2[j][0]);
                float a1 = fmaf(acc[mt][j][1], inv256, pb2[j][1]);
                float a2 = fmaf(acc[mt][j][2], inv256, pb2[j][0]);
                float a3 = fmaf(acc[mt][j][3], inv256, pb2[j][1]);
                int col = ng * 32 + j * 8 + 2 * t;
                int r = mt * 16 + g;
                *reinterpret_cast<uint16_t*>(smem_raw + SM_H2 + r * HS + col) =
                    tanh16_e4m3(a1, a0);
                *reinterpret_cast<uint16_t*>(smem_raw + SM_H2 + (r + 8) * HS + col) =
                    tanh16_e4m3(a3, a2);
            }
        __syncthreads();   // bar B: h2 ready

        // ---- GEMM3 (e4m3): [32,256] @ W3[256,64], acc3 = 256*(dx - b3) ----
        float acc3[2][4];
#pragma unroll
        for (int mt = 0; mt < 2; ++mt)
#pragma unroll
            for (int u = 0; u < 4; ++u) acc3[mt][u] = 0.f;

#pragma unroll
        for (int kb = 0; kb < 8; ++kb) {
#pragma unroll
            for (int mt = 0; mt < 2; ++mt) {
                uint32_t a0, a1v, a2, a3;
                ldsm_x4(a0, a1v, a2, a3, h2a[mt] + kb * 32);
                qmma(acc3[mt], a0, a1v, a2, a3, wb3a[kb], wb3b[kb]);
            }
        }

        // E3: x += acc3*dts/256 + b3*dts ; store trajectory + refresh xb
#pragma unroll
        for (int mt = 0; mt < 2; ++mt) {
            int r = mt * 16 + g;
            int colb = ng * 8 + t * 2;
            xr[mt][0] += fmaf(acc3[mt][0], dts256, pb3d[0]);
            xr[mt][1] += fmaf(acc3[mt][1], dts256, pb3d[1]);
            xr[mt][2] += fmaf(acc3[mt][2], dts256, pb3d[0]);
            xr[mt][3] += fmaf(acc3[mt][3], dts256, pb3d[1]);
            float* orow = out + (long)(row0 + r) * ostride
                        + (long)(step + 1) * S_ + colb;
            __stcs(reinterpret_cast<float2*>(orow),
                   make_float2(xr[mt][0], xr[mt][1]));
            __stcs(reinterpret_cast<float2*>(orow + 8 * ostride),
                   make_float2(xr[mt][2], xr[mt][3]));
            int pidx = ng * 4 + t;
            xb[r * XSTR + pidx]       = pack_bf16(xr[mt][0], xr[mt][1]);
            xb[(r + 8) * XSTR + pidx] = pack_bf16(xr[mt][2], xr[mt][3]);
        }
        __syncthreads();   // bar C: xb ready for next step
    }
}

extern "C" void kernel_launch(void* const* d_in, const int* in_sizes, int n_in,
                              void* d_out, int out_size)
{
    (void)in_sizes; (void)n_in; (void)out_size;
    const float* x0       = (const float*)d_in[0];
    const float* W1       = (const float*)d_in[1];
    const float* b1       = (const float*)d_in[2];
    const float* W2       = (const float*)d_in[3];
    const float* b2       = (const float*)d_in[4];
    const float* W3       = (const float*)d_in[5];
    const float* b3       = (const float*)d_in[6];
    const float* dt_scale = (const float*)d_in[7];
    const int*   nsteps   = (const int*)d_in[8];
    float*       out      = (float*)d_out;

    cudaFuncSetAttribute(neuralode_persistent_kernel,
                         cudaFuncAttributeMaxDynamicSharedMemorySize, SMEM_BYTES);
    neuralode_persistent_kernel<<<CTAS, NTH, SMEM_BYTES>>>(
        x0, W1, b1, W2, b2, W3, b3, dt_scale, nsteps, out);
}